// round 12
// baseline (speedup 1.0000x reference)
#include <cuda_runtime.h>

typedef unsigned long long ull;

#define B_     128
#define QN     16
#define LN     2048
#define EMB_   128
#define KN     11
#define TPB    512
#define NW     16              // warps per CTA
#define WD     64              // docs per warp per pass
#define DPP    1024            // docs per pass
#define EC     16              // e values per chunk
#define NC     8               // chunks per pass (EMB_/EC)
#define WBUF   (WD*EC)         // words per warp stage buffer (1024 = 4KB)

// ---------------- packed f32x2 helpers ----------------
__device__ __forceinline__ void fma2(ull& d, ull a, ull b) {
    asm("fma.rn.f32x2 %0, %1, %2, %0;" : "+l"(d) : "l"(a), "l"(b));
}
__device__ __forceinline__ ull fma2o(ull a, ull b, ull c) {
    ull r; asm("fma.rn.f32x2 %0, %1, %2, %3;" : "=l"(r) : "l"(a), "l"(b), "l"(c)); return r;
}
__device__ __forceinline__ ull add2(ull a, ull b) {
    ull r; asm("add.rn.f32x2 %0, %1, %2;" : "=l"(r) : "l"(a), "l"(b)); return r;
}
__device__ __forceinline__ ull mul2(ull a, ull b) {
    ull r; asm("mul.rn.f32x2 %0, %1, %2;" : "=l"(r) : "l"(a), "l"(b)); return r;
}
__device__ __forceinline__ ull pack2(float lo, float hi) {
    ull r; asm("mov.b64 %0, {%1, %2};" : "=l"(r) : "f"(lo), "f"(hi)); return r;
}
__device__ __forceinline__ float2 unpack2(ull v) {
    float2 r; asm("mov.b64 {%0, %1}, %2;" : "=f"(r.x), "=f"(r.y) : "l"(v)); return r;
}
__device__ __forceinline__ float ex2a(float x) {
    float r; asm("ex2.approx.f32 %0, %1;" : "=f"(r) : "f"(x)); return r;
}
__device__ __forceinline__ float lg2a(float x) {
    float r; asm("lg2.approx.f32 %0, %1;" : "=f"(r) : "f"(x)); return r;
}
__device__ __forceinline__ ull ex2p(ull a) {      // packed 2^x
    float2 f = unpack2(a);
    return pack2(ex2a(f.x), ex2a(f.y));
}

// ---------------- cp.async helpers ----------------
__device__ __forceinline__ unsigned smaddr(const void* p) {
    unsigned r;
    asm("{ .reg .u64 t; cvta.to.shared.u64 t, %1; cvt.u32.u64 %0, t; }"
        : "=r"(r) : "l"(p));
    return r;
}
__device__ __forceinline__ void cp16(unsigned dst, const void* src) {
    asm volatile("cp.async.cg.shared.global [%0], [%1], 16;" :: "r"(dst), "l"(src));
}
__device__ __forceinline__ void cp_commit() { asm volatile("cp.async.commit_group;"); }
__device__ __forceinline__ void cp_wait1()  { asm volatile("cp.async.wait_group 1;"); }
__device__ __forceinline__ void cp_wait0()  { asm volatile("cp.async.wait_group 0;"); }

// word offset of (doc, quarter) in a warp stage buffer, XOR-swizzled
__device__ __forceinline__ int sw_off(int doc, int q) {
    return doc * EC + ((q ^ ((doc >> 1) & 3)) << 2);
}

// stage one 16-e chunk of this warp's 64 docs into buffer `buf`
#define STAGE_CHUNK(buf, ch) do {                                              \
    _Pragma("unroll")                                                          \
    for (int i_ = 0; i_ < 8; ++i_)                                             \
        cp16(wstage_u32 + 4u*((buf)*WBUF + sw_off((lane >> 2) + 8*i_, q4)),    \
             emb + (size_t)gid_s[i_]*EMB_ + (ch)*EC + q4*4);                   \
    cp_commit(); } while (0)

// RBF pooling over 2 adjacent sims (packed), 11 centers via geometric
// recurrence from the middle center (mu5 = 0): only 3 packed EX2 seeds.
//   E = exp(-50 s^2)            (value at k=5)
//   G = exp( 20 s - 2)          (ascend factor; G *= e^-4 each step)
//   H = exp(-20 s - 2)          (descend factor; H *= e^-4 each step)
#define RBF_ITER(it) do {                                                      \
    float2 s01 = *(const float2*)(sims + w*DPP + 2*lane + 64*(it));            \
    ull S  = pack2(s01.x, s01.y);                                              \
    ull m  = mul2(S, S);                                                       \
    ull E  = ex2p(mul2(m, CE));                                                \
    ull G  = ex2p(fma2o(S, CP20, CM2));                                        \
    ull H  = ex2p(fma2o(S, CN20, CM2));                                        \
    pk2[5] = add2(pk2[5], E);                                                  \
    ull Eu = E;                                                                \
    Eu = mul2(Eu, G); pk2[6]  = add2(pk2[6],  Eu); G = mul2(G, CE4);           \
    Eu = mul2(Eu, G); pk2[7]  = add2(pk2[7],  Eu); G = mul2(G, CE4);           \
    Eu = mul2(Eu, G); pk2[8]  = add2(pk2[8],  Eu); G = mul2(G, CE4);           \
    Eu = mul2(Eu, G); pk2[9]  = add2(pk2[9],  Eu); G = mul2(G, CE4);           \
    Eu = mul2(Eu, G); pk2[10] = add2(pk2[10], Eu);                             \
    ull Ed = E;                                                                \
    Ed = mul2(Ed, H); pk2[4]  = add2(pk2[4],  Ed); H = mul2(H, CE4);           \
    Ed = mul2(Ed, H); pk2[3]  = add2(pk2[3],  Ed); H = mul2(H, CE4);           \
    Ed = mul2(Ed, H); pk2[2]  = add2(pk2[2],  Ed); H = mul2(H, CE4);           \
    Ed = mul2(Ed, H); pk2[1]  = add2(pk2[1],  Ed); H = mul2(H, CE4);           \
    Ed = mul2(Ed, H); pk2[0]  = add2(pk2[0],  Ed);                             \
    } while (0)

extern "C" __global__ void __launch_bounds__(TPB, 1)
knrm_fused(const int* __restrict__ queries,
           const int* __restrict__ docs,
           const float* __restrict__ emb,
           const float* __restrict__ W,
           const float* __restrict__ bias,
           float* __restrict__ out)
{
    extern __shared__ __align__(16) float sm[];
    float* qsT   = sm;                          // [128][16]       8 KB (transposed [e][q])
    float* sims  = sm + EMB_*QN;                // [16][1024]     64 KB
    float* stage = sims + QN*DPP;               // 16 warps x 2 x 4KB = 128 KB
    float* nsq   = stage + NW*2*WBUF;           // [16]
    float* parts = nsq + QN;                    // [16]

    const int b    = blockIdx.x;
    const int tid  = threadIdx.x;
    const int lane = tid & 31;
    const int w    = tid >> 5;                  // warp id; owns docs [w*64,w*64+64) and query w for RBF

    const unsigned wstage_u32 = smaddr(stage) + 4u * (unsigned)(w * 2 * WBUF);
    float* wstage = stage + w * 2 * WBUF;
    const int q4 = lane & 3;                    // staging quarter (16B)

    // ---------- startup: pass-0 gids + chunk-0 staging in flight FIRST ----------
    int gid_s[8];
    {
        const int base = b*LN + w*WD;
        #pragma unroll
        for (int i = 0; i < 8; ++i)
            gid_s[i] = docs[base + (lane >> 2) + 8*i];
    }
    STAGE_CHUNK(0, 0);                          // overlaps the whole query stage below

    // ---------- stage 1: gather + normalize queries into transposed smem ----------
    if (tid < QN) nsq[tid] = 0.0f;
    __syncthreads();
    {
        const int q1 = tid & 15;                // query
        const int c1 = tid >> 4;                // 4-float chunk (0..31)
        const int qi = queries[b*QN + q1];
        float4 v = *(const float4*)(emb + (size_t)qi*EMB_ + c1*4);
        float ssq = v.x*v.x + v.y*v.y + v.z*v.z + v.w*v.w;
        ssq += __shfl_xor_sync(0xffffffffu, ssq, 16);
        if (lane < 16) atomicAdd(&nsq[q1], ssq);
        __syncthreads();
        float n  = nsq[q1];
        float rn = (n > 0.0f) ? rsqrtf(n) : 0.0f;   // padding row -> sim = 0
        qsT[(c1*4+0)*QN + q1] = v.x*rn;
        qsT[(c1*4+1)*QN + q1] = v.y*rn;
        qsT[(c1*4+2)*QN + q1] = v.z*rn;
        qsT[(c1*4+3)*QN + q1] = v.w*rn;
    }
    __syncthreads();

    ull pk2[KN];
    #pragma unroll
    for (int k = 0; k < KN; ++k) pk2[k] = 0ull;
    // log2-domain seed constants (ex2 computes 2^x)
    const ull CE   = pack2(-72.13475204444817f, -72.13475204444817f);  // -50*log2(e)
    const ull CP20 = pack2( 28.853900817779268f, 28.853900817779268f); //  20*log2(e)
    const ull CN20 = pack2(-28.853900817779268f,-28.853900817779268f); // -20*log2(e)
    const ull CM2  = pack2(-2.8853900817779268f,-2.8853900817779268f); //  -2*log2(e)
    const ull CE4  = pack2(0.018315638888734179f, 0.018315638888734179f); // e^-4

    #pragma unroll 1
    for (int pass = 0; pass < 2; ++pass) {
        ull acc0[8], acc1[8], ssA = 0ull, ssB = 0ull;
        #pragma unroll
        for (int i = 0; i < 8; ++i) { acc0[i] = 0ull; acc1[i] = 0ull; }

        #pragma unroll 1
        for (int c = 0; c < NC; ++c) {
            __syncwarp();                        // all lanes done reading buf (c+1)&1 (chunk c-1)
            if (c + 1 < NC) {
                STAGE_CHUNK((c + 1) & 1, c + 1);
                cp_wait1();
            } else {
                cp_wait0();
            }
            __syncwarp();                        // chunk c data visible warp-wide

            // ---------- compute chunk c: 16 e's, 2 docs x 16 queries ----------
            const float* sbuf = wstage + (c & 1)*WBUF;
            ulonglong2 a0 = *(const ulonglong2*)(sbuf + sw_off(lane,      0));
            ulonglong2 a1 = *(const ulonglong2*)(sbuf + sw_off(lane + 32, 0));
            #pragma unroll
            for (int j = 0; j < 4; ++j) {
                ulonglong2 b0, b1;
                if (j < 3) {                     // prefetch next granule over this one's math
                    b0 = *(const ulonglong2*)(sbuf + sw_off(lane,      j + 1));
                    b1 = *(const ulonglong2*)(sbuf + sw_off(lane + 32, j + 1));
                }
                fma2(ssA, a0.x, a0.x); fma2(ssA, a0.y, a0.y);
                fma2(ssB, a1.x, a1.x); fma2(ssB, a1.y, a1.y);
                float2 e01 = unpack2(a0.x);
                float2 e23 = unpack2(a0.y);
                float2 f01 = unpack2(a1.x);
                float2 f23 = unpack2(a1.y);
                #pragma unroll
                for (int jj = 0; jj < 4; ++jj) {
                    float x0 = (jj==0)?e01.x:(jj==1)?e01.y:(jj==2)?e23.x:e23.y;
                    float x1 = (jj==0)?f01.x:(jj==1)?f01.y:(jj==2)?f23.x:f23.y;
                    ull A0 = pack2(x0, x0);
                    ull A1 = pack2(x1, x1);
                    const ulonglong2* qrow =
                        (const ulonglong2*)(qsT + (c*EC + j*4 + jj)*QN);
                    ulonglong2 qa = qrow[0];
                    ulonglong2 qb = qrow[1];
                    fma2(acc0[0], A0, qa.x); fma2(acc0[1], A0, qa.y);
                    fma2(acc0[2], A0, qb.x); fma2(acc0[3], A0, qb.y);
                    fma2(acc1[0], A1, qa.x); fma2(acc1[1], A1, qa.y);
                    fma2(acc1[2], A1, qb.x); fma2(acc1[3], A1, qb.y);
                    ulonglong2 qc = qrow[2];
                    ulonglong2 qd = qrow[3];
                    fma2(acc0[4], A0, qc.x); fma2(acc0[5], A0, qc.y);
                    fma2(acc0[6], A0, qd.x); fma2(acc0[7], A0, qd.y);
                    fma2(acc1[4], A1, qc.x); fma2(acc1[5], A1, qc.y);
                    fma2(acc1[6], A1, qd.x); fma2(acc1[7], A1, qd.y);
                }
                a0 = b0; a1 = b1;
            }

            // RBF of pass-0 sims interleaved into pass-1 dot (warp-local, no barrier)
            if (pass == 1) {
                RBF_ITER(2*c);
                RBF_ITER(2*c + 1);
            }
        }

        // ---------- inter-pass overlap: pass-1 gids + its chunk-0 staging NOW ----------
        if (pass == 0) {
            const int base = b*LN + DPP + w*WD;
            #pragma unroll
            for (int i = 0; i < 8; ++i)
                gid_s[i] = docs[base + (lane >> 2) + 8*i];
            STAGE_CHUNK(0, 0);
        }

        // ---------- norms + sims transpose (the only CTA-wide sync points) ----------
        {
            float2 na = unpack2(ssA);
            float2 nb = unpack2(ssB);
            float n0 = na.x + na.y;
            float n1 = nb.x + nb.y;
            float rd0 = (n0 > 0.0f) ? rsqrtf(n0) : 0.0f;  // padding doc -> sim 0
            float rd1 = (n1 > 0.0f) ? rsqrtf(n1) : 0.0f;

            if (pass == 1) __syncthreads();      // all warps done reading pass-0 sims
            const int col = w*WD + lane;
            #pragma unroll
            for (int qp = 0; qp < 8; ++qp) {
                float2 f0 = unpack2(acc0[qp]);
                float2 f1 = unpack2(acc1[qp]);
                sims[(2*qp  )*DPP + col]      = f0.x * rd0;
                sims[(2*qp+1)*DPP + col]      = f0.y * rd0;
                sims[(2*qp  )*DPP + col + 32] = f1.x * rd1;
                sims[(2*qp+1)*DPP + col + 32] = f1.y * rd1;
            }
        }
        __syncthreads();                         // sims visible to all warps
    }

    // ---------- RBF over pass-1 sims (exposed tail, now fma-light) ----------
    #pragma unroll 2
    for (int it = 0; it < 16; ++it) RBF_ITER(it);

    // ---------- epilogue: per-warp (per-query) reduce, log, W, sigmoid ----------
    float part = 0.0f;
    #pragma unroll
    for (int k = 0; k < KN; ++k) {
        float2 h = unpack2(pk2[k]);
        float v = h.x + h.y;
        v += __shfl_xor_sync(0xffffffffu, v, 16);
        v += __shfl_xor_sync(0xffffffffu, v, 8);
        v += __shfl_xor_sync(0xffffffffu, v, 4);
        v += __shfl_xor_sync(0xffffffffu, v, 2);
        v += __shfl_xor_sync(0xffffffffu, v, 1);
        part += __ldg(W + k) * (lg2a(v) * 0.6931471805599453f);
    }
    if (lane == 0) parts[w] = part;
    __syncthreads();
    if (tid == 0) {
        float s = __ldg(bias);
        #pragma unroll
        for (int i = 0; i < NW; ++i) s += parts[i];
        out[b] = 1.0f / (1.0f + __expf(-s));
    }
}

extern "C" void kernel_launch(void* const* d_in, const int* in_sizes, int n_in,
                              void* d_out, int out_size)
{
    const int*   queries = (const int*)d_in[0];
    const int*   docs    = (const int*)d_in[1];
    const float* emb     = (const float*)d_in[2];
    const float* W       = (const float*)d_in[3];
    const float* bias    = (const float*)d_in[4];
    float*       out     = (float*)d_out;

    const int smem = (EMB_*QN + QN*DPP + NW*2*WBUF + 2*QN) * (int)sizeof(float); // ~200 KB
    cudaFuncSetAttribute(knrm_fused, cudaFuncAttributeMaxDynamicSharedMemorySize, smem);

    knrm_fused<<<B_, TPB, smem>>>(queries, docs, emb, W, bias, out);
}

// round 13
// speedup vs baseline: 1.4944x; 1.4944x over previous
#include <cuda_runtime.h>

typedef unsigned long long ull;

#define B_     128
#define QN     16
#define LN     2048
#define EMB_   128
#define KN     11
#define TPB    512
#define NW     16              // warps per CTA
#define WD     64              // docs per warp per pass
#define DPP    1024            // docs per pass
#define EC     16              // e values per chunk
#define NC     8               // chunks per pass (EMB_/EC)
#define WBUF   (WD*EC)         // words per warp stage buffer (1024 = 4KB)

// ---------------- packed f32x2 helpers ----------------
__device__ __forceinline__ void fma2(ull& d, ull a, ull b) {
    asm("fma.rn.f32x2 %0, %1, %2, %0;" : "+l"(d) : "l"(a), "l"(b));
}
__device__ __forceinline__ ull fma2o(ull a, ull b, ull c) {
    ull r; asm("fma.rn.f32x2 %0, %1, %2, %3;" : "=l"(r) : "l"(a), "l"(b), "l"(c)); return r;
}
__device__ __forceinline__ ull add2(ull a, ull b) {
    ull r; asm("add.rn.f32x2 %0, %1, %2;" : "=l"(r) : "l"(a), "l"(b)); return r;
}
__device__ __forceinline__ ull mul2(ull a, ull b) {
    ull r; asm("mul.rn.f32x2 %0, %1, %2;" : "=l"(r) : "l"(a), "l"(b)); return r;
}
__device__ __forceinline__ ull pack2(float lo, float hi) {
    ull r; asm("mov.b64 %0, {%1, %2};" : "=l"(r) : "f"(lo), "f"(hi)); return r;
}
__device__ __forceinline__ float2 unpack2(ull v) {
    float2 r; asm("mov.b64 {%0, %1}, %2;" : "=f"(r.x), "=f"(r.y) : "l"(v)); return r;
}
__device__ __forceinline__ float ex2a(float x) {
    float r; asm("ex2.approx.f32 %0, %1;" : "=f"(r) : "f"(x)); return r;
}
__device__ __forceinline__ float lg2a(float x) {
    float r; asm("lg2.approx.f32 %0, %1;" : "=f"(r) : "f"(x)); return r;
}
__device__ __forceinline__ ull ex2p(ull a) {      // packed 2^x
    float2 f = unpack2(a);
    return pack2(ex2a(f.x), ex2a(f.y));
}

// ---------------- cp.async helpers ----------------
__device__ __forceinline__ unsigned smaddr(const void* p) {
    unsigned r;
    asm("{ .reg .u64 t; cvta.to.shared.u64 t, %1; cvt.u32.u64 %0, t; }"
        : "=r"(r) : "l"(p));
    return r;
}
__device__ __forceinline__ void cp16(unsigned dst, const void* src) {
    asm volatile("cp.async.cg.shared.global [%0], [%1], 16;" :: "r"(dst), "l"(src));
}
__device__ __forceinline__ void cp_commit() { asm volatile("cp.async.commit_group;"); }
__device__ __forceinline__ void cp_wait1()  { asm volatile("cp.async.wait_group 1;"); }
__device__ __forceinline__ void cp_wait0()  { asm volatile("cp.async.wait_group 0;"); }

// word offset of (doc, quarter) in a warp stage buffer, XOR-swizzled
__device__ __forceinline__ int sw_off(int doc, int q) {
    return doc * EC + ((q ^ ((doc >> 1) & 3)) << 2);
}

// stage one 16-e chunk of this warp's 64 docs into buffer `buf`
#define STAGE_CHUNK(buf, ch) do {                                              \
    _Pragma("unroll")                                                          \
    for (int i_ = 0; i_ < 8; ++i_)                                             \
        cp16(wstage_u32 + 4u*((buf)*WBUF + sw_off((lane >> 2) + 8*i_, q4)),    \
             emb + (size_t)gid_s[i_]*EMB_ + (ch)*EC + q4*4);                   \
    cp_commit(); } while (0)

// RBF pooling over 2 adjacent sims (packed), 11 centers via geometric
// recurrence seeded at the middle center (mu5 = 0). Only 3 packed EX2:
//   E = exp(-50 s^2)          value at k=5
//   G = exp( 20 s - 2)        ascend ratio (then G *= e^-4 per step)
//   H = exp(-20 s - 2)        descend ratio (seeded AFTER ascend; reuses G's reg)
// Live packed temps: S, E, G, T  (~8 scalar regs, same as R10's RBF temps).
#define RBF_ITER(it) do {                                                      \
    float2 s01 = *(const float2*)(sims + w*DPP + 2*lane + 64*(it));            \
    ull S  = pack2(s01.x, s01.y);                                              \
    ull E  = ex2p(mul2(mul2(S, S), CE));                                       \
    pk2[5] = add2(pk2[5], E);                                                  \
    ull G  = ex2p(fma2o(S, CP20, CM2));                                        \
    ull T  = mul2(E, G); pk2[6]  = add2(pk2[6],  T); G = mul2(G, CE4);         \
    T = mul2(T, G); pk2[7]  = add2(pk2[7],  T); G = mul2(G, CE4);              \
    T = mul2(T, G); pk2[8]  = add2(pk2[8],  T); G = mul2(G, CE4);              \
    T = mul2(T, G); pk2[9]  = add2(pk2[9],  T); G = mul2(G, CE4);              \
    T = mul2(T, G); pk2[10] = add2(pk2[10], T);                                \
    G  = ex2p(fma2o(S, CN20, CM2));                                            \
    T = mul2(E, G); pk2[4]  = add2(pk2[4],  T); G = mul2(G, CE4);              \
    T = mul2(T, G); pk2[3]  = add2(pk2[3],  T); G = mul2(G, CE4);              \
    T = mul2(T, G); pk2[2]  = add2(pk2[2],  T); G = mul2(G, CE4);              \
    T = mul2(T, G); pk2[1]  = add2(pk2[1],  T); G = mul2(G, CE4);              \
    T = mul2(T, G); pk2[0]  = add2(pk2[0],  T);                                \
    } while (0)

extern "C" __global__ void __launch_bounds__(TPB, 1)
knrm_fused(const int* __restrict__ queries,
           const int* __restrict__ docs,
           const float* __restrict__ emb,
           const float* __restrict__ W,
           const float* __restrict__ bias,
           float* __restrict__ out)
{
    extern __shared__ __align__(16) float sm[];
    float* qsT   = sm;                          // [128][16]       8 KB (transposed [e][q])
    float* sims  = sm + EMB_*QN;                // [16][1024]     64 KB
    float* stage = sims + QN*DPP;               // 16 warps x 2 x 4KB = 128 KB
    float* nsq   = stage + NW*2*WBUF;           // [16]
    float* parts = nsq + QN;                    // [16]

    const int b    = blockIdx.x;
    const int tid  = threadIdx.x;
    const int lane = tid & 31;
    const int w    = tid >> 5;                  // warp id; owns docs [w*64,w*64+64) and query w for RBF

    const unsigned wstage_u32 = smaddr(stage) + 4u * (unsigned)(w * 2 * WBUF);
    float* wstage = stage + w * 2 * WBUF;
    const int q4 = lane & 3;                    // staging quarter (16B)

    // ---------- startup: pass-0 gids + chunk-0 staging in flight FIRST ----------
    int gid_s[8];
    {
        const int base = b*LN + w*WD;
        #pragma unroll
        for (int i = 0; i < 8; ++i)
            gid_s[i] = docs[base + (lane >> 2) + 8*i];
    }
    STAGE_CHUNK(0, 0);                          // overlaps the whole query stage below

    // ---------- stage 1: gather + normalize queries into transposed smem ----------
    if (tid < QN) nsq[tid] = 0.0f;
    __syncthreads();
    {
        const int q1 = tid & 15;                // query
        const int c1 = tid >> 4;                // 4-float chunk (0..31)
        const int qi = queries[b*QN + q1];
        float4 v = *(const float4*)(emb + (size_t)qi*EMB_ + c1*4);
        float ssq = v.x*v.x + v.y*v.y + v.z*v.z + v.w*v.w;
        ssq += __shfl_xor_sync(0xffffffffu, ssq, 16);
        if (lane < 16) atomicAdd(&nsq[q1], ssq);
        __syncthreads();
        float n  = nsq[q1];
        float rn = (n > 0.0f) ? rsqrtf(n) : 0.0f;   // padding row -> sim = 0
        qsT[(c1*4+0)*QN + q1] = v.x*rn;
        qsT[(c1*4+1)*QN + q1] = v.y*rn;
        qsT[(c1*4+2)*QN + q1] = v.z*rn;
        qsT[(c1*4+3)*QN + q1] = v.w*rn;
    }
    __syncthreads();

    ull pk2[KN];
    #pragma unroll
    for (int k = 0; k < KN; ++k) pk2[k] = 0ull;
    // log2-domain seed constants (ex2 computes 2^x)
    const ull CE   = pack2(-72.13475204444817f, -72.13475204444817f);  // -50*log2(e)
    const ull CP20 = pack2( 28.853900817779268f, 28.853900817779268f); //  20*log2(e)
    const ull CN20 = pack2(-28.853900817779268f,-28.853900817779268f); // -20*log2(e)
    const ull CM2  = pack2(-2.8853900817779268f,-2.8853900817779268f); //  -2*log2(e)
    const ull CE4  = pack2(0.018315638888734179f, 0.018315638888734179f); // e^-4

    #pragma unroll 1
    for (int pass = 0; pass < 2; ++pass) {
        ull acc0[8], acc1[8], ssA = 0ull, ssB = 0ull;
        #pragma unroll
        for (int i = 0; i < 8; ++i) { acc0[i] = 0ull; acc1[i] = 0ull; }

        #pragma unroll 1
        for (int c = 0; c < NC; ++c) {
            __syncwarp();                        // all lanes done reading buf (c+1)&1 (chunk c-1)
            if (c + 1 < NC) {
                STAGE_CHUNK((c + 1) & 1, c + 1);
                cp_wait1();
            } else {
                cp_wait0();
            }
            __syncwarp();                        // chunk c data visible warp-wide

            // ---------- compute chunk c: 16 e's, 2 docs x 16 queries ----------
            const float* sbuf = wstage + (c & 1)*WBUF;
            #pragma unroll
            for (int j = 0; j < 4; ++j) {
                ulonglong2 a0 = *(const ulonglong2*)(sbuf + sw_off(lane,      j));
                ulonglong2 a1 = *(const ulonglong2*)(sbuf + sw_off(lane + 32, j));
                fma2(ssA, a0.x, a0.x); fma2(ssA, a0.y, a0.y);
                fma2(ssB, a1.x, a1.x); fma2(ssB, a1.y, a1.y);
                float2 e01 = unpack2(a0.x);
                float2 e23 = unpack2(a0.y);
                float2 f01 = unpack2(a1.x);
                float2 f23 = unpack2(a1.y);
                #pragma unroll
                for (int jj = 0; jj < 4; ++jj) {
                    float x0 = (jj==0)?e01.x:(jj==1)?e01.y:(jj==2)?e23.x:e23.y;
                    float x1 = (jj==0)?f01.x:(jj==1)?f01.y:(jj==2)?f23.x:f23.y;
                    ull A0 = pack2(x0, x0);
                    ull A1 = pack2(x1, x1);
                    const ulonglong2* qrow =
                        (const ulonglong2*)(qsT + (c*EC + j*4 + jj)*QN);
                    ulonglong2 qa = qrow[0];
                    ulonglong2 qb = qrow[1];
                    fma2(acc0[0], A0, qa.x); fma2(acc0[1], A0, qa.y);
                    fma2(acc0[2], A0, qb.x); fma2(acc0[3], A0, qb.y);
                    fma2(acc1[0], A1, qa.x); fma2(acc1[1], A1, qa.y);
                    fma2(acc1[2], A1, qb.x); fma2(acc1[3], A1, qb.y);
                    ulonglong2 qc = qrow[2];
                    ulonglong2 qd = qrow[3];
                    fma2(acc0[4], A0, qc.x); fma2(acc0[5], A0, qc.y);
                    fma2(acc0[6], A0, qd.x); fma2(acc0[7], A0, qd.y);
                    fma2(acc1[4], A1, qc.x); fma2(acc1[5], A1, qc.y);
                    fma2(acc1[6], A1, qd.x); fma2(acc1[7], A1, qd.y);
                }
            }

            // RBF of pass-0 sims interleaved into pass-1 dot (warp-local, no barrier)
            if (pass == 1) {
                RBF_ITER(2*c);
                RBF_ITER(2*c + 1);
            }
        }

        // ---------- inter-pass overlap: pass-1 gids + its chunk-0 staging NOW ----------
        if (pass == 0) {
            const int base = b*LN + DPP + w*WD;
            #pragma unroll
            for (int i = 0; i < 8; ++i)
                gid_s[i] = docs[base + (lane >> 2) + 8*i];
            STAGE_CHUNK(0, 0);
        }

        // ---------- norms + sims transpose (the only CTA-wide sync points) ----------
        {
            float2 na = unpack2(ssA);
            float2 nb = unpack2(ssB);
            float n0 = na.x + na.y;
            float n1 = nb.x + nb.y;
            float rd0 = (n0 > 0.0f) ? rsqrtf(n0) : 0.0f;  // padding doc -> sim 0
            float rd1 = (n1 > 0.0f) ? rsqrtf(n1) : 0.0f;

            if (pass == 1) __syncthreads();      // all warps done reading pass-0 sims
            const int col = w*WD + lane;
            #pragma unroll
            for (int qp = 0; qp < 8; ++qp) {
                float2 f0 = unpack2(acc0[qp]);
                float2 f1 = unpack2(acc1[qp]);
                sims[(2*qp  )*DPP + col]      = f0.x * rd0;
                sims[(2*qp+1)*DPP + col]      = f0.y * rd0;
                sims[(2*qp  )*DPP + col + 32] = f1.x * rd1;
                sims[(2*qp+1)*DPP + col + 32] = f1.y * rd1;
            }
        }
        __syncthreads();                         // sims visible to all warps
    }

    // ---------- RBF over pass-1 sims (exposed tail) ----------
    #pragma unroll 2
    for (int it = 0; it < 16; ++it) RBF_ITER(it);

    // ---------- epilogue: per-warp (per-query) reduce, log, W, sigmoid ----------
    float part = 0.0f;
    #pragma unroll
    for (int k = 0; k < KN; ++k) {
        float2 h = unpack2(pk2[k]);
        float v = h.x + h.y;
        v += __shfl_xor_sync(0xffffffffu, v, 16);
        v += __shfl_xor_sync(0xffffffffu, v, 8);
        v += __shfl_xor_sync(0xffffffffu, v, 4);
        v += __shfl_xor_sync(0xffffffffu, v, 2);
        v += __shfl_xor_sync(0xffffffffu, v, 1);
        part += __ldg(W + k) * (lg2a(v) * 0.6931471805599453f);
    }
    if (lane == 0) parts[w] = part;
    __syncthreads();
    if (tid == 0) {
        float s = __ldg(bias);
        #pragma unroll
        for (int i = 0; i < NW; ++i) s += parts[i];
        out[b] = 1.0f / (1.0f + __expf(-s));
    }
}

extern "C" void kernel_launch(void* const* d_in, const int* in_sizes, int n_in,
                              void* d_out, int out_size)
{
    const int*   queries = (const int*)d_in[0];
    const int*   docs    = (const int*)d_in[1];
    const float* emb     = (const float*)d_in[2];
    const float* W       = (const float*)d_in[3];
    const float* bias    = (const float*)d_in[4];
    float*       out     = (float*)d_out;

    const int smem = (EMB_*QN + QN*DPP + NW*2*WBUF + 2*QN) * (int)sizeof(float); // ~200 KB
    cudaFuncSetAttribute(knrm_fused, cudaFuncAttributeMaxDynamicSharedMemorySize, smem);

    knrm_fused<<<B_, TPB, smem>>>(queries, docs, emb, W, bias, out);
}

// round 15
// speedup vs baseline: 1.6328x; 1.0926x over previous
#include <cuda_runtime.h>

typedef unsigned long long ull;

#define B_     128
#define QN     16
#define LN     2048
#define EMB_   128
#define KN     11
#define TPB    512
#define NW     16              // warps per CTA
#define WD     64              // docs per warp per pass
#define DPP    1024            // docs per pass
#define EC     16              // e values per chunk
#define NC     8               // chunks per pass (EMB_/EC)
#define WBUF   (WD*EC)         // words per warp stage buffer (1024 = 4KB)

// ---------------- packed f32x2 helpers ----------------
__device__ __forceinline__ void fma2(ull& d, ull a, ull b) {
    asm("fma.rn.f32x2 %0, %1, %2, %0;" : "+l"(d) : "l"(a), "l"(b));
}
__device__ __forceinline__ ull fma2o(ull a, ull b, ull c) {
    ull r; asm("fma.rn.f32x2 %0, %1, %2, %3;" : "=l"(r) : "l"(a), "l"(b), "l"(c)); return r;
}
__device__ __forceinline__ ull add2(ull a, ull b) {
    ull r; asm("add.rn.f32x2 %0, %1, %2;" : "=l"(r) : "l"(a), "l"(b)); return r;
}
__device__ __forceinline__ ull mul2(ull a, ull b) {
    ull r; asm("mul.rn.f32x2 %0, %1, %2;" : "=l"(r) : "l"(a), "l"(b)); return r;
}
__device__ __forceinline__ ull pack2(float lo, float hi) {
    ull r; asm("mov.b64 %0, {%1, %2};" : "=l"(r) : "f"(lo), "f"(hi)); return r;
}
__device__ __forceinline__ float2 unpack2(ull v) {
    float2 r; asm("mov.b64 {%0, %1}, %2;" : "=f"(r.x), "=f"(r.y) : "l"(v)); return r;
}
__device__ __forceinline__ float ex2a(float x) {
    float r; asm("ex2.approx.f32 %0, %1;" : "=f"(r) : "f"(x)); return r;
}
__device__ __forceinline__ float lg2a(float x) {
    float r; asm("lg2.approx.f32 %0, %1;" : "=f"(r) : "f"(x)); return r;
}
__device__ __forceinline__ ull ex2p(ull a) {      // packed 2^x
    float2 f = unpack2(a);
    return pack2(ex2a(f.x), ex2a(f.y));
}

// ---------------- cp.async helpers ----------------
__device__ __forceinline__ unsigned smaddr(const void* p) {
    unsigned r;
    asm("{ .reg .u64 t; cvta.to.shared.u64 t, %1; cvt.u32.u64 %0, t; }"
        : "=r"(r) : "l"(p));
    return r;
}
__device__ __forceinline__ void cp16(unsigned dst, const void* src) {
    asm volatile("cp.async.cg.shared.global [%0], [%1], 16;" :: "r"(dst), "l"(src));
}
__device__ __forceinline__ void cp_commit() { asm volatile("cp.async.commit_group;"); }
__device__ __forceinline__ void cp_wait1()  { asm volatile("cp.async.wait_group 1;"); }
__device__ __forceinline__ void cp_wait0()  { asm volatile("cp.async.wait_group 0;"); }

// word offset of (doc, quarter) in a warp stage buffer, XOR-swizzled
__device__ __forceinline__ int sw_off(int doc, int q) {
    return doc * EC + ((q ^ ((doc >> 1) & 3)) << 2);
}

// stage one 16-e chunk of this warp's 64 docs into buffer `buf`
#define STAGE_CHUNK(buf, ch) do {                                              \
    _Pragma("unroll")                                                          \
    for (int i_ = 0; i_ < 8; ++i_)                                             \
        cp16(wstage_u32 + 4u*((buf)*WBUF + sw_off((lane >> 2) + 8*i_, q4)),    \
             emb + (size_t)gid_s[i_]*EMB_ + (ch)*EC + q4*4);                   \
    cp_commit(); } while (0)

// one 16-e chunk of the dot: 2 docs x 16 queries, packed accumulators
#define DOT_CHUNK(c) do {                                                      \
    const float* sbuf = wstage + ((c) & 1)*WBUF;                               \
    _Pragma("unroll")                                                          \
    for (int j = 0; j < 4; ++j) {                                              \
        ulonglong2 a0 = *(const ulonglong2*)(sbuf + sw_off(lane,      j));     \
        ulonglong2 a1 = *(const ulonglong2*)(sbuf + sw_off(lane + 32, j));     \
        fma2(ssA, a0.x, a0.x); fma2(ssA, a0.y, a0.y);                          \
        fma2(ssB, a1.x, a1.x); fma2(ssB, a1.y, a1.y);                          \
        float2 e01 = unpack2(a0.x);                                            \
        float2 e23 = unpack2(a0.y);                                            \
        float2 f01 = unpack2(a1.x);                                            \
        float2 f23 = unpack2(a1.y);                                            \
        _Pragma("unroll")                                                      \
        for (int jj = 0; jj < 4; ++jj) {                                       \
            float x0 = (jj==0)?e01.x:(jj==1)?e01.y:(jj==2)?e23.x:e23.y;        \
            float x1 = (jj==0)?f01.x:(jj==1)?f01.y:(jj==2)?f23.x:f23.y;        \
            ull A0 = pack2(x0, x0);                                            \
            ull A1 = pack2(x1, x1);                                            \
            const ulonglong2* qrow =                                           \
                (const ulonglong2*)(qsT + ((c)*EC + j*4 + jj)*QN);             \
            ulonglong2 qa = qrow[0];                                           \
            ulonglong2 qb = qrow[1];                                           \
            fma2(acc0[0], A0, qa.x); fma2(acc0[1], A0, qa.y);                  \
            fma2(acc0[2], A0, qb.x); fma2(acc0[3], A0, qb.y);                  \
            fma2(acc1[0], A1, qa.x); fma2(acc1[1], A1, qa.y);                  \
            fma2(acc1[2], A1, qb.x); fma2(acc1[3], A1, qb.y);                  \
            ulonglong2 qc = qrow[2];                                           \
            ulonglong2 qd = qrow[3];                                           \
            fma2(acc0[4], A0, qc.x); fma2(acc0[5], A0, qc.y);                  \
            fma2(acc0[6], A0, qd.x); fma2(acc0[7], A0, qd.y);                  \
            fma2(acc1[4], A1, qc.x); fma2(acc1[5], A1, qc.y);                  \
            fma2(acc1[6], A1, qd.x); fma2(acc1[7], A1, qd.y);                  \
        }                                                                      \
    } } while (0)

// Two independent RBF iterations, chains interleaved for ILP.
// Geometric recurrence from middle center (mu5 = 0): 3 packed EX2 per iter.
#define RBF_ITER2(itA, itB) do {                                               \
    float2 sA = *(const float2*)(sims + w*DPP + 2*lane + 64*(itA));            \
    float2 sB = *(const float2*)(sims + w*DPP + 2*lane + 64*(itB));            \
    ull SA = pack2(sA.x, sA.y);                                                \
    ull SB = pack2(sB.x, sB.y);                                                \
    ull EA = ex2p(mul2(mul2(SA, SA), CE));                                     \
    ull EB = ex2p(mul2(mul2(SB, SB), CE));                                     \
    pk2[5] = add2(add2(pk2[5], EA), EB);                                       \
    ull GA = ex2p(fma2o(SA, CP20, CM2));                                       \
    ull GB = ex2p(fma2o(SB, CP20, CM2));                                       \
    ull TA = mul2(EA, GA);  ull TB = mul2(EB, GB);                             \
    pk2[6]  = add2(add2(pk2[6],  TA), TB); GA = mul2(GA, CE4); GB = mul2(GB, CE4); \
    TA = mul2(TA, GA); TB = mul2(TB, GB);                                      \
    pk2[7]  = add2(add2(pk2[7],  TA), TB); GA = mul2(GA, CE4); GB = mul2(GB, CE4); \
    TA = mul2(TA, GA); TB = mul2(TB, GB);                                      \
    pk2[8]  = add2(add2(pk2[8],  TA), TB); GA = mul2(GA, CE4); GB = mul2(GB, CE4); \
    TA = mul2(TA, GA); TB = mul2(TB, GB);                                      \
    pk2[9]  = add2(add2(pk2[9],  TA), TB); GA = mul2(GA, CE4); GB = mul2(GB, CE4); \
    TA = mul2(TA, GA); TB = mul2(TB, GB);                                      \
    pk2[10] = add2(add2(pk2[10], TA), TB);                                     \
    GA = ex2p(fma2o(SA, CN20, CM2));                                           \
    GB = ex2p(fma2o(SB, CN20, CM2));                                           \
    TA = mul2(EA, GA);  TB = mul2(EB, GB);                                     \
    pk2[4]  = add2(add2(pk2[4],  TA), TB); GA = mul2(GA, CE4); GB = mul2(GB, CE4); \
    TA = mul2(TA, GA); TB = mul2(TB, GB);                                      \
    pk2[3]  = add2(add2(pk2[3],  TA), TB); GA = mul2(GA, CE4); GB = mul2(GB, CE4); \
    TA = mul2(TA, GA); TB = mul2(TB, GB);                                      \
    pk2[2]  = add2(add2(pk2[2],  TA), TB); GA = mul2(GA, CE4); GB = mul2(GB, CE4); \
    TA = mul2(TA, GA); TB = mul2(TB, GB);                                      \
    pk2[1]  = add2(add2(pk2[1],  TA), TB); GA = mul2(GA, CE4); GB = mul2(GB, CE4); \
    TA = mul2(TA, GA); TB = mul2(TB, GB);                                      \
    pk2[0]  = add2(add2(pk2[0],  TA), TB);                                     \
    } while (0)

extern "C" __global__ void __launch_bounds__(TPB, 1)
knrm_fused(const int* __restrict__ queries,
           const int* __restrict__ docs,
           const float* __restrict__ emb,
           const float* __restrict__ W,
           const float* __restrict__ bias,
           float* __restrict__ out)
{
    extern __shared__ __align__(16) float sm[];
    float* qsT   = sm;                          // [128][16]       8 KB (transposed [e][q])
    float* sims  = sm + EMB_*QN;                // [16][1024]     64 KB
    float* stage = sims + QN*DPP;               // 16 warps x 2 x 4KB = 128 KB
    float* nsq   = stage + NW*2*WBUF;           // [16]
    float* parts = nsq + QN;                    // [16]

    const int b    = blockIdx.x;
    const int tid  = threadIdx.x;
    const int lane = tid & 31;
    const int w    = tid >> 5;                  // warp id; owns docs [w*64,w*64+64) and query w for RBF

    const unsigned wstage_u32 = smaddr(stage) + 4u * (unsigned)(w * 2 * WBUF);
    float* wstage = stage + w * 2 * WBUF;
    const int q4 = lane & 3;                    // staging quarter (16B)

    // ---------- startup: pass-0 gids + chunk-0 staging in flight FIRST ----------
    int gid_s[8];
    {
        const int base = b*LN + w*WD;
        #pragma unroll
        for (int i = 0; i < 8; ++i)
            gid_s[i] = docs[base + (lane >> 2) + 8*i];
    }
    STAGE_CHUNK(0, 0);                          // overlaps the whole query stage below

    // ---------- stage 1: gather + normalize queries into transposed smem ----------
    if (tid < QN) nsq[tid] = 0.0f;
    __syncthreads();
    {
        const int q1 = tid & 15;                // query
        const int c1 = tid >> 4;                // 4-float chunk (0..31)
        const int qi = queries[b*QN + q1];
        float4 v = *(const float4*)(emb + (size_t)qi*EMB_ + c1*4);
        float ssq = v.x*v.x + v.y*v.y + v.z*v.z + v.w*v.w;
        ssq += __shfl_xor_sync(0xffffffffu, ssq, 16);
        if (lane < 16) atomicAdd(&nsq[q1], ssq);
        __syncthreads();
        float n  = nsq[q1];
        float rn = (n > 0.0f) ? rsqrtf(n) : 0.0f;   // padding row -> sim = 0
        qsT[(c1*4+0)*QN + q1] = v.x*rn;
        qsT[(c1*4+1)*QN + q1] = v.y*rn;
        qsT[(c1*4+2)*QN + q1] = v.z*rn;
        qsT[(c1*4+3)*QN + q1] = v.w*rn;
    }
    __syncthreads();

    // ================= PASS 0 (no RBF: pk2/constants NOT live here) =================
    {
        ull acc0[8], acc1[8], ssA = 0ull, ssB = 0ull;
        #pragma unroll
        for (int i = 0; i < 8; ++i) { acc0[i] = 0ull; acc1[i] = 0ull; }

        #pragma unroll 1
        for (int c = 0; c < NC; ++c) {
            __syncwarp();                        // all lanes done reading buf (c+1)&1 (chunk c-1)
            if (c + 1 < NC) {
                STAGE_CHUNK((c + 1) & 1, c + 1);
                cp_wait1();
            } else {
                cp_wait0();
            }
            __syncwarp();                        // chunk c data visible warp-wide
            DOT_CHUNK(c);
        }

        // pass-1 gids + its chunk-0 staging (hides under norms/writes/barrier)
        {
            const int base = b*LN + DPP + w*WD;
            #pragma unroll
            for (int i = 0; i < 8; ++i)
                gid_s[i] = docs[base + (lane >> 2) + 8*i];
            STAGE_CHUNK(0, 0);
        }

        float2 na = unpack2(ssA);
        float2 nb = unpack2(ssB);
        float n0 = na.x + na.y;
        float n1 = nb.x + nb.y;
        float rd0 = (n0 > 0.0f) ? rsqrtf(n0) : 0.0f;  // padding doc -> sim 0
        float rd1 = (n1 > 0.0f) ? rsqrtf(n1) : 0.0f;
        const int col = w*WD + lane;
        #pragma unroll
        for (int qp = 0; qp < 8; ++qp) {
            float2 f0 = unpack2(acc0[qp]);
            float2 f1 = unpack2(acc1[qp]);
            sims[(2*qp  )*DPP + col]      = f0.x * rd0;
            sims[(2*qp+1)*DPP + col]      = f0.y * rd0;
            sims[(2*qp  )*DPP + col + 32] = f1.x * rd1;
            sims[(2*qp+1)*DPP + col + 32] = f1.y * rd1;
        }
    }
    __syncthreads();                             // pass-0 sims visible to all warps

    // ================= PASS 1 + RBF + epilogue =================
    {
        ull pk2[KN];
        #pragma unroll
        for (int k = 0; k < KN; ++k) pk2[k] = 0ull;
        // log2-domain seed constants (ex2 computes 2^x)
        const ull CE   = pack2(-72.13475204444817f, -72.13475204444817f);  // -50*log2(e)
        const ull CP20 = pack2( 28.853900817779268f, 28.853900817779268f); //  20*log2(e)
        const ull CN20 = pack2(-28.853900817779268f,-28.853900817779268f); // -20*log2(e)
        const ull CM2  = pack2(-2.8853900817779268f,-2.8853900817779268f); //  -2*log2(e)
        const ull CE4  = pack2(0.018315638888734179f, 0.018315638888734179f); // e^-4

        ull acc0[8], acc1[8], ssA = 0ull, ssB = 0ull;
        #pragma unroll
        for (int i = 0; i < 8; ++i) { acc0[i] = 0ull; acc1[i] = 0ull; }

        #pragma unroll 1
        for (int c = 0; c < NC; ++c) {
            __syncwarp();
            if (c + 1 < NC) STAGE_CHUNK((c + 1) & 1, c + 1);
            // RBF of pass-0 sims here: covers staging latency, no stage-buffer access
            RBF_ITER2(2*c, 2*c + 1);
            if (c + 1 < NC) cp_wait1(); else cp_wait0();
            __syncwarp();                        // chunk c data visible warp-wide
            DOT_CHUNK(c);
        }

        // ---------- norms + sims transpose ----------
        {
            float2 na = unpack2(ssA);
            float2 nb = unpack2(ssB);
            float n0 = na.x + na.y;
            float n1 = nb.x + nb.y;
            float rd0 = (n0 > 0.0f) ? rsqrtf(n0) : 0.0f;
            float rd1 = (n1 > 0.0f) ? rsqrtf(n1) : 0.0f;

            __syncthreads();                     // all warps done reading pass-0 sims
            const int col = w*WD + lane;
            #pragma unroll
            for (int qp = 0; qp < 8; ++qp) {
                float2 f0 = unpack2(acc0[qp]);
                float2 f1 = unpack2(acc1[qp]);
                sims[(2*qp  )*DPP + col]      = f0.x * rd0;
                sims[(2*qp+1)*DPP + col]      = f0.y * rd0;
                sims[(2*qp  )*DPP + col + 32] = f1.x * rd1;
                sims[(2*qp+1)*DPP + col + 32] = f1.y * rd1;
            }
        }
        __syncthreads();                         // pass-1 sims visible to all warps

        // ---------- RBF over pass-1 sims (exposed tail, interleaved pairs) ----------
        #pragma unroll 1
        for (int it = 0; it < 16; it += 2) RBF_ITER2(it, it + 1);

        // ---------- epilogue: per-warp (per-query) reduce, log, W, sigmoid ----------
        float part = 0.0f;
        #pragma unroll
        for (int k = 0; k < KN; ++k) {
            float2 h = unpack2(pk2[k]);
            float v = h.x + h.y;
            v += __shfl_xor_sync(0xffffffffu, v, 16);
            v += __shfl_xor_sync(0xffffffffu, v, 8);
            v += __shfl_xor_sync(0xffffffffu, v, 4);
            v += __shfl_xor_sync(0xffffffffu, v, 2);
            v += __shfl_xor_sync(0xffffffffu, v, 1);
            part += __ldg(W + k) * (lg2a(v) * 0.6931471805599453f);
        }
        if (lane == 0) parts[w] = part;
    }
    __syncthreads();
    if (tid == 0) {
        float s = __ldg(bias);
        #pragma unroll
        for (int i = 0; i < NW; ++i) s += parts[i];
        out[b] = 1.0f / (1.0f + __expf(-s));
    }
}

extern "C" void kernel_launch(void* const* d_in, const int* in_sizes, int n_in,
                              void* d_out, int out_size)
{
    const int*   queries = (const int*)d_in[0];
    const int*   docs    = (const int*)d_in[1];
    const float* emb     = (const float*)d_in[2];
    const float* W       = (const float*)d_in[3];
    const float* bias    = (const float*)d_in[4];
    float*       out     = (float*)d_out;

    const int smem = (EMB_*QN + QN*DPP + NW*2*WBUF + 2*QN) * (int)sizeof(float); // ~200 KB
    cudaFuncSetAttribute(knrm_fused, cudaFuncAttributeMaxDynamicSharedMemorySize, smem);

    knrm_fused<<<B_, TPB, smem>>>(queries, docs, emb, W, bias, out);
}